// round 8
// baseline (speedup 1.0000x reference)
#include <cuda_runtime.h>
#include <stdint.h>

// NeighborNoiser — partitionable threefry2x32, key (0,42), fold = x0^x1 (bit-exact R2+).
// R8: lift the issue cap. Model: issue <= 0.5 / alu_share (alu rt=2). Shift mix to
// 2 wide-mul chains : 2 SHF chains per pixel -> alu share ~0.60, cap ~0.83.
// Keep 4 px/thread (16 chains), launch_bounds(256,4), IADD3-fused key schedule.

#define N1 25165824u                    // 8*3*1024*1024

__device__ __forceinline__ uint32_t rotl(uint32_t v, const int d) {
    return __funnelshift_l(v, v, d);
}

#define RS(d) { x0 += x1; x1 = rotl(x1,(d)) ^ x0; }

// SHF-rotate chain (alu-heavy)
__device__ __forceinline__ uint32_t tf_shf(uint32_t ctr) {
    const uint32_t ks1 = 42u, ks2 = 0x1BD11BDAu ^ 42u;
    uint32_t x1 = ctr + ks1;
    uint32_t x0 = x1;                               // round-1 add with x0 = 0
    x1 = rotl(x1,13) ^ x0;
    RS(15) RS(26) RS(6)
    x1 += ks2 + 1u;  x0 = x0 + x1 + ks1;  x1 = rotl(x1,17) ^ x0;
    RS(29) RS(16) RS(24)
    x1 += 2u;        x0 = x0 + x1 + ks2;  x1 = rotl(x1,13) ^ x0;
    RS(15) RS(26) RS(6)
    x1 += ks1 + 3u;  x0 = x0 + x1;        x1 = rotl(x1,17) ^ x0;   // ks0 = 0
    RS(29) RS(16) RS(24)
    x1 += ks2 + 4u;  x0 = x0 + x1 + ks1;  x1 = rotl(x1,13) ^ x0;
    RS(15) RS(26) RS(6)
    x1 += 5u;
    return (x0 + ks2) ^ x1;
}

// wide-mul rotate: IMAD.WIDE (fma pipe) + single LOP3 ((lo|hi)^x0)
__device__ __forceinline__ uint32_t wrot(uint32_t v, uint32_t pw) {
    uint32_t lo, hi;
    asm("{\n\t.reg .b64 w;\n\tmul.wide.u32 w, %2, %3;\n\tmov.b64 {%0, %1}, w;\n\t}"
        : "=r"(lo), "=r"(hi) : "r"(v), "r"(pw));
    return lo | hi;
}

#define RW(p) { x0 += x1; x1 = wrot(x1,(p)) ^ x0; }

__device__ __forceinline__ uint32_t tf_wide(uint32_t ctr) {
    const uint32_t ks1 = 42u, ks2 = 0x1BD11BDAu ^ 42u;
    const uint32_t p13 = 1u<<13, p15 = 1u<<15, p26 = 1u<<26, p6 = 1u<<6;
    const uint32_t p17 = 1u<<17, p29 = 1u<<29, p16 = 1u<<16, p24 = 1u<<24;
    uint32_t x1 = ctr + ks1;
    uint32_t x0 = x1;
    x1 = wrot(x1,p13) ^ x0;
    RW(p15) RW(p26) RW(p6)
    x1 += ks2 + 1u;  x0 = x0 + x1 + ks1;  x1 = wrot(x1,p17) ^ x0;
    RW(p29) RW(p16) RW(p24)
    x1 += 2u;        x0 = x0 + x1 + ks2;  x1 = wrot(x1,p13) ^ x0;
    RW(p15) RW(p26) RW(p6)
    x1 += ks1 + 3u;  x0 = x0 + x1;        x1 = wrot(x1,p17) ^ x0;
    RW(p29) RW(p16) RW(p24)
    x1 += ks2 + 4u;  x0 = x0 + x1 + ks1;  x1 = wrot(x1,p13) ^ x0;
    RW(p15) RW(p26) RW(p6)
    x1 += 5u;
    return (x0 + ks2) ^ x1;
}

// IMAD.HI (hi(bits*2^23)+exp, fma pipe) then FADD
__device__ __forceinline__ float u01(uint32_t bits) {
    return __uint_as_float(__umulhi(bits, 1u << 23) + 0x3f800000u) - 1.0f;
}

__global__ __launch_bounds__(256, 4)
void neighbor_noiser_kernel(const float* __restrict__ t, float* __restrict__ out) {
    uint32_t gid  = blockIdx.x * blockDim.x + threadIdx.x;
    uint32_t base = gid * 4u;                   // 4 adjacent pixels in one row

    uint32_t plane = base >> 20;
    uint32_t pos   = base & 0xFFFFFu;
    uint32_t y     = pos >> 10;
    uint32_t x     = pos & 1023u;               // multiple of 4

    const float* p = t + ((size_t)plane << 20);
    uint32_t yu = (y == 0u)    ? 0u    : y - 1u;
    uint32_t yd = (y == 1023u) ? 1023u : y + 1u;
    const float* rowc = p + (y << 10);

    float4 up4 = __ldg((const float4*)(p + (yu << 10) + x));
    float4 dn4 = __ldg((const float4*)(p + (yd << 10) + x));
    float4 ct4 = __ldg((const float4*)(rowc + x));
    float lf_e = (x == 0u)     ? ct4.x : __ldg(rowc + x - 1u);
    float rt_e = (x == 1020u)  ? ct4.w : __ldg(rowc + x + 4u);

    // 16 chains: per pixel, up+down wide (fma), left+right SHF (alu)
    uint32_t bu0 = tf_wide(base);
    uint32_t bu1 = tf_wide(base + 1u);
    uint32_t bu2 = tf_wide(base + 2u);
    uint32_t bu3 = tf_wide(base + 3u);
    uint32_t bd0 = tf_wide(base + N1);
    uint32_t bd1 = tf_wide(base + N1 + 1u);
    uint32_t bd2 = tf_wide(base + N1 + 2u);
    uint32_t bd3 = tf_wide(base + N1 + 3u);
    uint32_t bl0 = tf_shf(base + 2u*N1);
    uint32_t bl1 = tf_shf(base + 2u*N1 + 1u);
    uint32_t bl2 = tf_shf(base + 2u*N1 + 2u);
    uint32_t bl3 = tf_shf(base + 2u*N1 + 3u);
    uint32_t br0 = tf_shf(base + 3u*N1);
    uint32_t br1 = tf_shf(base + 3u*N1 + 1u);
    uint32_t br2 = tf_shf(base + 3u*N1 + 2u);
    uint32_t br3 = tf_shf(base + 3u*N1 + 3u);

    float upv[4] = {up4.x, up4.y, up4.z, up4.w};
    float dnv[4] = {dn4.x, dn4.y, dn4.z, dn4.w};
    float lfv[4] = {lf_e,  ct4.x, ct4.y, ct4.z};
    float rtv[4] = {ct4.y, ct4.z, ct4.w, rt_e};
    uint32_t buv[4] = {bu0, bu1, bu2, bu3};
    uint32_t bdv[4] = {bd0, bd1, bd2, bd3};
    uint32_t blv[4] = {bl0, bl1, bl2, bl3};
    uint32_t brv[4] = {br0, br1, br2, br3};

    float res[4];
#pragma unroll
    for (int i = 0; i < 4; i++) {
        float ur = u01(buv[i]);
        float dr = u01(bdv[i]);
        float lr = u01(blv[i]);
        float rr = u01(brv[i]);
        float s   = (ur + dr) + (lr + rr);
        float num = fmaf(upv[i], ur, fmaf(dnv[i], dr, fmaf(lfv[i], lr, rtv[i] * rr)));
        res[i] = __fdividef(num, s);
    }

    *reinterpret_cast<float4*>(out + base) = make_float4(res[0], res[1], res[2], res[3]);
}

extern "C" void kernel_launch(void* const* d_in, const int* in_sizes, int n_in,
                              void* d_out, int out_size) {
    const float* t = (const float*)d_in[0];
    float* out = (float*)d_out;
    (void)in_sizes; (void)n_in; (void)out_size;

    const uint32_t threads = 256;
    const uint32_t blocks = (N1 / 4u) / threads;   // 24576, exact
    neighbor_noiser_kernel<<<blocks, threads>>>(t, out);
}

// round 9
// speedup vs baseline: 1.0475x; 1.0475x over previous
#include <cuda_runtime.h>
#include <stdint.h>

// NeighborNoiser — partitionable threefry2x32, key (0,42), fold = x0^x1 (bit-exact R2+).
// R9: 2:2 wide:SHF pipe balance (alu share ~0.5) at FULL occupancy.
// 2 px/thread (8 chains), __launch_bounds__(256,8) caps regs at 32 -> 8 CTA/SM.

#define N1 25165824u                    // 8*3*1024*1024

__device__ __forceinline__ uint32_t rotl(uint32_t v, const int d) {
    return __funnelshift_l(v, v, d);
}

#define RS(d) { x0 += x1; x1 = rotl(x1,(d)) ^ x0; }

// SHF-rotate chain (alu-heavy)
__device__ __forceinline__ uint32_t tf_shf(uint32_t ctr) {
    const uint32_t ks1 = 42u, ks2 = 0x1BD11BDAu ^ 42u;
    uint32_t x1 = ctr + ks1;
    uint32_t x0 = x1;                               // round-1 add with x0 = 0
    x1 = rotl(x1,13) ^ x0;
    RS(15) RS(26) RS(6)
    x1 += ks2 + 1u;  x0 = x0 + x1 + ks1;  x1 = rotl(x1,17) ^ x0;
    RS(29) RS(16) RS(24)
    x1 += 2u;        x0 = x0 + x1 + ks2;  x1 = rotl(x1,13) ^ x0;
    RS(15) RS(26) RS(6)
    x1 += ks1 + 3u;  x0 = x0 + x1;        x1 = rotl(x1,17) ^ x0;   // ks0 = 0
    RS(29) RS(16) RS(24)
    x1 += ks2 + 4u;  x0 = x0 + x1 + ks1;  x1 = rotl(x1,13) ^ x0;
    RS(15) RS(26) RS(6)
    x1 += 5u;
    return (x0 + ks2) ^ x1;
}

// wide-mul rotate: IMAD.WIDE (fma pipe, immediate multiplier) + single LOP3
__device__ __forceinline__ uint32_t wrot(uint32_t v, uint32_t pw) {
    uint32_t lo, hi;
    asm("{\n\t.reg .b64 w;\n\tmul.wide.u32 w, %2, %3;\n\tmov.b64 {%0, %1}, w;\n\t}"
        : "=r"(lo), "=r"(hi) : "r"(v), "r"(pw));
    return lo | hi;
}

#define RW(p) { x0 += x1; x1 = wrot(x1,(p)) ^ x0; }

__device__ __forceinline__ uint32_t tf_wide(uint32_t ctr) {
    const uint32_t ks1 = 42u, ks2 = 0x1BD11BDAu ^ 42u;
    const uint32_t p13 = 1u<<13, p15 = 1u<<15, p26 = 1u<<26, p6 = 1u<<6;
    const uint32_t p17 = 1u<<17, p29 = 1u<<29, p16 = 1u<<16, p24 = 1u<<24;
    uint32_t x1 = ctr + ks1;
    uint32_t x0 = x1;
    x1 = wrot(x1,p13) ^ x0;
    RW(p15) RW(p26) RW(p6)
    x1 += ks2 + 1u;  x0 = x0 + x1 + ks1;  x1 = wrot(x1,p17) ^ x0;
    RW(p29) RW(p16) RW(p24)
    x1 += 2u;        x0 = x0 + x1 + ks2;  x1 = wrot(x1,p13) ^ x0;
    RW(p15) RW(p26) RW(p6)
    x1 += ks1 + 3u;  x0 = x0 + x1;        x1 = wrot(x1,p17) ^ x0;
    RW(p29) RW(p16) RW(p24)
    x1 += ks2 + 4u;  x0 = x0 + x1 + ks1;  x1 = wrot(x1,p13) ^ x0;
    RW(p15) RW(p26) RW(p6)
    x1 += 5u;
    return (x0 + ks2) ^ x1;
}

// bits>>9 as IMAD.HI (fma pipe); exponent OR as add (pipe-flexible)
__device__ __forceinline__ float u01(uint32_t bits) {
    return __uint_as_float(__umulhi(bits, 1u << 23) + 0x3f800000u) - 1.0f;
}

__global__ __launch_bounds__(256, 8)
void neighbor_noiser_kernel(const float* __restrict__ t, float* __restrict__ out) {
    uint32_t gid  = blockIdx.x * blockDim.x + threadIdx.x;
    uint32_t base = gid * 2u;                   // 2 adjacent pixels in one row

    uint32_t plane = base >> 20;
    uint32_t pos   = base & 0xFFFFFu;
    uint32_t y     = pos >> 10;
    uint32_t x     = pos & 1023u;               // even

    const float* p = t + ((size_t)plane << 20);
    uint32_t yu = (y == 0u)    ? 0u    : y - 1u;
    uint32_t yd = (y == 1023u) ? 1023u : y + 1u;
    const float* rowc = p + (y << 10);

    float2 up2 = __ldg((const float2*)(p + (yu << 10) + x));
    float2 dn2 = __ldg((const float2*)(p + (yd << 10) + x));
    float2 ct2 = __ldg((const float2*)(rowc + x));
    float lf_e = (x == 0u)    ? ct2.x : __ldg(rowc + x - 1u);
    float rt_e = (x == 1022u) ? ct2.y : __ldg(rowc + x + 2u);

    // 8 chains: per pixel, up+down wide (fma rotate), left+right SHF (alu rotate)
    uint32_t j0 = base, j1 = base + 1u;
    uint32_t bu0 = tf_wide(j0);
    uint32_t bu1 = tf_wide(j1);
    uint32_t bd0 = tf_wide(j0 + N1);
    uint32_t bd1 = tf_wide(j1 + N1);
    uint32_t bl0 = tf_shf(j0 + 2u*N1);
    uint32_t bl1 = tf_shf(j1 + 2u*N1);
    uint32_t br0 = tf_shf(j0 + 3u*N1);
    uint32_t br1 = tf_shf(j1 + 3u*N1);

    float ur0 = u01(bu0), dr0 = u01(bd0), lr0 = u01(bl0), rr0 = u01(br0);
    float ur1 = u01(bu1), dr1 = u01(bd1), lr1 = u01(bl1), rr1 = u01(br1);

    float s0   = (ur0 + dr0) + (lr0 + rr0);
    float num0 = fmaf(up2.x, ur0, fmaf(dn2.x, dr0, fmaf(lf_e, lr0, ct2.y * rr0)));
    float s1   = (ur1 + dr1) + (lr1 + rr1);
    float num1 = fmaf(up2.y, ur1, fmaf(dn2.y, dr1, fmaf(ct2.x, lr1, rt_e * rr1)));

    float2 o = make_float2(__fdividef(num0, s0), __fdividef(num1, s1));
    *reinterpret_cast<float2*>(out + base) = o;
}

extern "C" void kernel_launch(void* const* d_in, const int* in_sizes, int n_in,
                              void* d_out, int out_size) {
    const float* t = (const float*)d_in[0];
    float* out = (float*)d_out;
    (void)in_sizes; (void)n_in; (void)out_size;

    const uint32_t threads = 256;
    const uint32_t blocks = (N1 / 2u) / threads;   // 49152, exact
    neighbor_noiser_kernel<<<blocks, threads>>>(t, out);
}

// round 10
// speedup vs baseline: 1.1208x; 1.0700x over previous
#include <cuda_runtime.h>
#include <stdint.h>

// NeighborNoiser — partitionable threefry2x32, key (0,42), fold = x0^x1 (bit-exact R2+).
// R10 = R7 (best: 255us, 4px/thread, 1 wide : 3 SHF chains, launch_bounds(256,4))
// + u01 fused to a single IMAD.HI (hi(bits*2^23) + exp_bits in the addend slot).
// Model: issue rate is pinned ~0.75 (structural); dur tracks issued-slot count only.

#define N1 25165824u                    // 8*3*1024*1024

__device__ __forceinline__ uint32_t rotl(uint32_t v, const int d) {
    return __funnelshift_l(v, v, d);
}

#define RS(d) { x0 += x1; x1 = rotl(x1,(d)) ^ x0; }

// SHF-rotate chain (alu-heavy)
__device__ __forceinline__ uint32_t tf_shf(uint32_t ctr) {
    const uint32_t ks1 = 42u, ks2 = 0x1BD11BDAu ^ 42u;
    uint32_t x1 = ctr + ks1;
    uint32_t x0 = x1;                               // round-1 add with x0 = 0
    x1 = rotl(x1,13) ^ x0;
    RS(15) RS(26) RS(6)
    x1 += ks2 + 1u;  x0 = x0 + x1 + ks1;  x1 = rotl(x1,17) ^ x0;   // IADD3 fuse
    RS(29) RS(16) RS(24)
    x1 += 2u;        x0 = x0 + x1 + ks2;  x1 = rotl(x1,13) ^ x0;
    RS(15) RS(26) RS(6)
    x1 += ks1 + 3u;  x0 = x0 + x1;        x1 = rotl(x1,17) ^ x0;   // ks0 = 0
    RS(29) RS(16) RS(24)
    x1 += ks2 + 4u;  x0 = x0 + x1 + ks1;  x1 = rotl(x1,13) ^ x0;
    RS(15) RS(26) RS(6)
    x1 += 5u;
    return (x0 + ks2) ^ x1;
}

// wide-mul rotate: IMAD.WIDE (fma pipe) + single LOP3 ((lo|hi)^x0)
__device__ __forceinline__ uint32_t wrot(uint32_t v, uint32_t pw) {
    uint32_t lo, hi;
    asm("{\n\t.reg .b64 w;\n\tmul.wide.u32 w, %2, %3;\n\tmov.b64 {%0, %1}, w;\n\t}"
        : "=r"(lo), "=r"(hi) : "r"(v), "r"(pw));
    return lo | hi;
}

#define RW(p) { x0 += x1; x1 = wrot(x1,(p)) ^ x0; }

__device__ __forceinline__ uint32_t tf_wide(uint32_t ctr) {
    const uint32_t ks1 = 42u, ks2 = 0x1BD11BDAu ^ 42u;
    const uint32_t p13 = 1u<<13, p15 = 1u<<15, p26 = 1u<<26, p6 = 1u<<6;
    const uint32_t p17 = 1u<<17, p29 = 1u<<29, p16 = 1u<<16, p24 = 1u<<24;
    uint32_t x1 = ctr + ks1;
    uint32_t x0 = x1;
    x1 = wrot(x1,p13) ^ x0;
    RW(p15) RW(p26) RW(p6)
    x1 += ks2 + 1u;  x0 = x0 + x1 + ks1;  x1 = wrot(x1,p17) ^ x0;
    RW(p29) RW(p16) RW(p24)
    x1 += 2u;        x0 = x0 + x1 + ks2;  x1 = wrot(x1,p13) ^ x0;
    RW(p15) RW(p26) RW(p6)
    x1 += ks1 + 3u;  x0 = x0 + x1;        x1 = wrot(x1,p17) ^ x0;
    RW(p29) RW(p16) RW(p24)
    x1 += ks2 + 4u;  x0 = x0 + x1 + ks1;  x1 = wrot(x1,p13) ^ x0;
    RW(p15) RW(p26) RW(p6)
    x1 += 5u;
    return (x0 + ks2) ^ x1;
}

// Single IMAD.HI: hi(bits * 2^23) + 0x3f800000  ->  float in [1,2); then -1.
__device__ __forceinline__ float u01(uint32_t bits) {
    uint32_t m;
    asm("mad.hi.u32 %0, %1, %2, %3;"
        : "=r"(m) : "r"(bits), "r"(1u << 23), "r"(0x3f800000u));
    return __uint_as_float(m) - 1.0f;
}

__global__ __launch_bounds__(256, 4)
void neighbor_noiser_kernel(const float* __restrict__ t, float* __restrict__ out) {
    uint32_t gid  = blockIdx.x * blockDim.x + threadIdx.x;
    uint32_t base = gid * 4u;                   // 4 adjacent pixels in one row

    uint32_t plane = base >> 20;
    uint32_t pos   = base & 0xFFFFFu;
    uint32_t y     = pos >> 10;
    uint32_t x     = pos & 1023u;               // multiple of 4

    const float* p = t + ((size_t)plane << 20);
    uint32_t yu = (y == 0u)    ? 0u    : y - 1u;
    uint32_t yd = (y == 1023u) ? 1023u : y + 1u;
    const float* rowc = p + (y << 10);

    float4 up4 = __ldg((const float4*)(p + (yu << 10) + x));
    float4 dn4 = __ldg((const float4*)(p + (yd << 10) + x));
    float4 ct4 = __ldg((const float4*)(rowc + x));
    float lf_e = (x == 0u)     ? ct4.x : __ldg(rowc + x - 1u);
    float rt_e = (x == 1020u)  ? ct4.w : __ldg(rowc + x + 4u);

    // 16 independent hash chains: per pixel, up-chain wide, other 3 SHF.
    uint32_t bu0 = tf_wide(base);
    uint32_t bu1 = tf_wide(base + 1u);
    uint32_t bu2 = tf_wide(base + 2u);
    uint32_t bu3 = tf_wide(base + 3u);
    uint32_t bd0 = tf_shf(base + N1);
    uint32_t bd1 = tf_shf(base + N1 + 1u);
    uint32_t bd2 = tf_shf(base + N1 + 2u);
    uint32_t bd3 = tf_shf(base + N1 + 3u);
    uint32_t bl0 = tf_shf(base + 2u*N1);
    uint32_t bl1 = tf_shf(base + 2u*N1 + 1u);
    uint32_t bl2 = tf_shf(base + 2u*N1 + 2u);
    uint32_t bl3 = tf_shf(base + 2u*N1 + 3u);
    uint32_t br0 = tf_shf(base + 3u*N1);
    uint32_t br1 = tf_shf(base + 3u*N1 + 1u);
    uint32_t br2 = tf_shf(base + 3u*N1 + 2u);
    uint32_t br3 = tf_shf(base + 3u*N1 + 3u);

    float upv[4] = {up4.x, up4.y, up4.z, up4.w};
    float dnv[4] = {dn4.x, dn4.y, dn4.z, dn4.w};
    float lfv[4] = {lf_e,  ct4.x, ct4.y, ct4.z};
    float rtv[4] = {ct4.y, ct4.z, ct4.w, rt_e};
    uint32_t buv[4] = {bu0, bu1, bu2, bu3};
    uint32_t bdv[4] = {bd0, bd1, bd2, bd3};
    uint32_t blv[4] = {bl0, bl1, bl2, bl3};
    uint32_t brv[4] = {br0, br1, br2, br3};

    float res[4];
#pragma unroll
    for (int i = 0; i < 4; i++) {
        float ur = u01(buv[i]);
        float dr = u01(bdv[i]);
        float lr = u01(blv[i]);
        float rr = u01(brv[i]);
        float s   = (ur + dr) + (lr + rr);
        float num = fmaf(upv[i], ur, fmaf(dnv[i], dr, fmaf(lfv[i], lr, rtv[i] * rr)));
        res[i] = __fdividef(num, s);
    }

    *reinterpret_cast<float4*>(out + base) = make_float4(res[0], res[1], res[2], res[3]);
}

extern "C" void kernel_launch(void* const* d_in, const int* in_sizes, int n_in,
                              void* d_out, int out_size) {
    const float* t = (const float*)d_in[0];
    float* out = (float*)d_out;
    (void)in_sizes; (void)n_in; (void)out_size;

    const uint32_t threads = 256;
    const uint32_t blocks = (N1 / 4u) / threads;   // 24576, exact
    neighbor_noiser_kernel<<<blocks, threads>>>(t, out);
}